// round 14
// baseline (speedup 1.0000x reference)
#include <cuda_runtime.h>
#include <cuda_bf16.h>
#include <cstdint>

#define NN 8192
#define EE 131072
#define ND 128
#define HD 256
#define NKP (ND / 2)                // 64 kpairs per row (u32 = 2 bf16)
#define ADJ_WORDS (NN * NN / 32)    // 8 MiB bitmap
#define MAXROW 64                   // distinct-degree cap (Poisson(16): P>=64 ~ 1e-20)

// Scratch (no allocations allowed — device globals per harness rules).
// INVARIANT across calls: g_adj all-zero and g_deg all-zero at entry.
__device__ unsigned g_adj[ADJ_WORDS];
__device__ int      g_deg[NN];             // EXTRA distinct neighbors (true deg = +1)
__device__ int      g_nbr[NN * MAXROW];    // 2 MB compact adjacency
__device__ float    g_xs[NN * ND];
// Operands in VECTORIZED fragment-major layout: each lane's 4 m16n8k16 chunks
// are one contiguous uint4 -> single LDG.128 per fragment set.
//   A (hi/lo separate): g_a*4[(rt*8+kt)*32 + lane] = {a0,a1,a2,a3}
//   B (hi+lo packed):   g_b4 [(nt*8+kt)*32 + lane] = {bh0,bh1,bl0,bl1}
__device__ uint4 g_ahi4[NN * NKP / 4];
__device__ uint4 g_alo4[NN * NKP / 4];
__device__ uint4 g_b4[(HD / 8) * 8 * 32];
__device__ int   g_is64;

// ---------------------------------------------------------------------------
// Fragment addressing (u32-granular, for the writers).
// ---------------------------------------------------------------------------
__device__ __forceinline__ int a_u32(int i, int kp) {
    int rt = i >> 4, kt = kp >> 3;
    int r16 = i & 15, k8 = kp & 7;
    int chunk = ((k8 >> 2) << 1) | (r16 >> 3);
    int lane = (r16 & 7) * 4 + (k8 & 3);
    return (((rt * 8 + kt) * 32 + lane) << 2) + chunk;
}

// ---------------------------------------------------------------------------
// int64 vs int32 detection (values in [0,8192): int64 LE buffer has every odd
// 32-bit word == 0; int32 has random indices there).
// ---------------------------------------------------------------------------
__device__ __forceinline__ int detect_is64_block(const unsigned* ei, int* s_ok) {
    if (threadIdx.x == 0) *s_ok = 1;
    __syncthreads();
    if (threadIdx.x < 64 && ei[2 * threadIdx.x + 1] != 0u) *s_ok = 0;
    __syncthreads();
    return *s_ok;
}

__device__ __forceinline__ void decode_edge(const void* ei, int is64, int e,
                                            int& s, int& t) {
    if (is64) {
        const long long* p = (const long long*)ei;
        s = (int)p[e];
        t = (int)p[EE + e];
    } else {
        const int* p = (const int*)ei;
        s = p[e];
        t = p[EE + e];
    }
}

// split (vx, vy) into packed bf16x2 hi and lo
__device__ __forceinline__ void split2(float vx, float vy, uint32_t& hi, uint32_t& lo) {
    __nv_bfloat162 h2 = __floats2bfloat162_rn(vx, vy);
    float r0 = vx - __bfloat162float(__low2bfloat16(h2));
    float r1 = vy - __bfloat162float(__high2bfloat16(h2));
    __nv_bfloat162 l2 = __floats2bfloat162_rn(r0, r1);
    hi = *(uint32_t*)&h2;
    lo = *(uint32_t*)&l2;
}

__global__ void __launch_bounds__(256) k_scatter(const void* __restrict__ ei) {
    __shared__ int s_ok;
    int is64 = detect_is64_block((const unsigned*)ei, &s_ok);
    if (blockIdx.x == 0 && threadIdx.x == 0) g_is64 = is64;

    int e = blockIdx.x * blockDim.x + threadIdx.x;
    if (e >= EE) return;
    int s, t;
    decode_edge(ei, is64, e, s, t);
    unsigned idx  = (unsigned)s * NN + (unsigned)t;
    unsigned mask = 1u << (idx & 31u);
    unsigned old  = atomicOr(&g_adj[idx >> 5], mask);
    if (!(old & mask)) {
        int slot = atomicAdd(&g_deg[s], 1);
        if (slot < MAXROW) g_nbr[s * MAXROW + slot] = t;
    }
}

// Fused: bitmap cleanup [0,512) + xs = D^-1/2 x [512,1024) + W split [1024,1088)
#define PB_CLEAN (EE / 256)                    // 512
#define PB_SCALE ((NN * ND / 8) / 256)         // 512
#define PB_WS    ((HD * NKP) / 256)            // 64
__global__ void __launch_bounds__(256) k_post(const void* __restrict__ ei,
                                              const float* __restrict__ x,
                                              const float* __restrict__ W) {
    if (blockIdx.x < PB_CLEAN) {
        int is64 = g_is64;
        int e = blockIdx.x * 256 + threadIdx.x;
        int s, t;
        decode_edge(ei, is64, e, s, t);
        g_adj[((unsigned)s * NN + (unsigned)t) >> 5] = 0u;   // races benign
    } else if (blockIdx.x < PB_CLEAN + PB_SCALE) {
        int gid = (blockIdx.x - PB_CLEAN) * 256 + threadIdx.x;
        int q = 2 * gid;
        int i = q >> 5;
        float dinv = rsqrtf((float)(g_deg[i] + 1));
        float4 v0 = __ldg((const float4*)x + q);
        float4 v1 = __ldg((const float4*)x + q + 1);
        v0.x *= dinv; v0.y *= dinv; v0.z *= dinv; v0.w *= dinv;
        v1.x *= dinv; v1.y *= dinv; v1.z *= dinv; v1.w *= dinv;
        ((float4*)g_xs)[q]     = v0;
        ((float4*)g_xs)[q + 1] = v1;
    } else {
        int e = (blockIdx.x - PB_CLEAN - PB_SCALE) * 256 + threadIdx.x;
        int h = e >> 6, p = e & 63;                           // col h, kpair p
        float2 v = *(const float2*)(W + (size_t)h * ND + 2 * p);
        uint32_t hi, lo; split2(v.x, v.y, hi, lo);
        int nt = h >> 3, kt = p >> 3;
        int n8 = h & 7, k8 = p & 7;
        int b = k8 >> 2;
        int lane = n8 * 4 + (k8 & 3);
        uint32_t* b4u = (uint32_t*)g_b4;
        int base = ((nt * 8 + kt) * 32 + lane) << 2;
        b4u[base + b]     = hi;
        b4u[base + 2 + b] = lo;
    }
}

// mid = A_hat @ x (two warps per row, half-split); epilogue writes the bf16
// hi/lo split of mid in vectorized fragment layout; resets g_deg (invariant).
__global__ void __launch_bounds__(256) k_aggregate() {
    __shared__ __align__(16) float4 part[4 * 32];
    int warp = threadIdx.x >> 5;
    int lane = threadIdx.x & 31;
    int r    = warp >> 1;
    int half = warp & 1;
    int i = blockIdx.x * 4 + r;

    int dext = g_deg[i];
    int n = min(dext, MAXROW);
    int k  = half ? (n >> 1) : 0;
    int k1 = half ? n        : (n >> 1);

    const float4* __restrict__ xs4 = (const float4*)g_xs;
    const int* __restrict__ lst = g_nbr + i * MAXROW;

    float4 acc = make_float4(0.f, 0.f, 0.f, 0.f);
    if (!half) acc = xs4[i * 32 + lane];

    for (; k + 7 < k1; k += 8) {
        int j0 = __ldg(lst + k + 0), j1 = __ldg(lst + k + 1);
        int j2 = __ldg(lst + k + 2), j3 = __ldg(lst + k + 3);
        int j4 = __ldg(lst + k + 4), j5 = __ldg(lst + k + 5);
        int j6 = __ldg(lst + k + 6), j7 = __ldg(lst + k + 7);
        float4 a0 = xs4[j0 * 32 + lane], a1 = xs4[j1 * 32 + lane];
        float4 a2 = xs4[j2 * 32 + lane], a3 = xs4[j3 * 32 + lane];
        float4 a4 = xs4[j4 * 32 + lane], a5 = xs4[j5 * 32 + lane];
        float4 a6 = xs4[j6 * 32 + lane], a7 = xs4[j7 * 32 + lane];
        acc.x += ((a0.x + a1.x) + (a2.x + a3.x)) + ((a4.x + a5.x) + (a6.x + a7.x));
        acc.y += ((a0.y + a1.y) + (a2.y + a3.y)) + ((a4.y + a5.y) + (a6.y + a7.y));
        acc.z += ((a0.z + a1.z) + (a2.z + a3.z)) + ((a4.z + a5.z) + (a6.z + a7.z));
        acc.w += ((a0.w + a1.w) + (a2.w + a3.w)) + ((a4.w + a5.w) + (a6.w + a7.w));
    }
    for (; k < k1; k++) {
        int j = __ldg(lst + k);
        float4 a = xs4[j * 32 + lane];
        acc.x += a.x; acc.y += a.y; acc.z += a.z; acc.w += a.w;
    }

    if (half) part[r * 32 + lane] = acc;
    __syncthreads();
    if (!half) {
        float4 p = part[r * 32 + lane];
        float dinv = rsqrtf((float)(dext + 1));
        acc.x = (acc.x + p.x) * dinv;
        acc.y = (acc.y + p.y) * dinv;
        acc.z = (acc.z + p.z) * dinv;
        acc.w = (acc.w + p.w) * dinv;
        uint32_t h0, l0, h1, l1;
        split2(acc.x, acc.y, h0, l0);              // kpair 2*lane
        split2(acc.z, acc.w, h1, l1);              // kpair 2*lane+1
        uint32_t* ahi = (uint32_t*)g_ahi4;
        uint32_t* alo = (uint32_t*)g_alo4;
        int a0 = a_u32(i, 2 * lane);
        int a1 = a_u32(i, 2 * lane + 1);
        ahi[a0] = h0; ahi[a1] = h1;
        alo[a0] = l0; alo[a1] = l1;
        if (lane == 0) g_deg[i] = 0;
    }
}

// ===========================================================================
// HMMA GEMM. CTA = 16 rows x 256 cols, 4 warps; warp = 16 rows x 64 cols.
// ALL A fragments (8 ktiles x hi/lo = 16 LDG.128) preloaded before the
// mainloop -> a single L2 round trip with MLP=16 instead of 8 serial ones
// (R12/R13 showed issue stuck at 7% regardless of occupancy: the per-ktile
// A-load L2 latency was the critical path). Mainloop touches only L1-hit B.
// Fully unrolled; 3-pass bf16 split (hh + hl + lh), fp32 accum.
// ===========================================================================
#define MMA3(A0,A1,A2,A3, B0,B1, C)                                          \
    asm volatile("mma.sync.aligned.m16n8k16.row.col.f32.bf16.bf16.f32 "      \
        "{%0,%1,%2,%3},{%4,%5,%6,%7},{%8,%9},{%0,%1,%2,%3};"                 \
        : "+f"(C[0]), "+f"(C[1]), "+f"(C[2]), "+f"(C[3])                     \
        : "r"(A0), "r"(A1), "r"(A2), "r"(A3), "r"(B0), "r"(B1))

__global__ void __launch_bounds__(128) k_gemm_mma(float* __restrict__ out) {
    int lane = threadIdx.x & 31;
    int wid  = threadIdx.x >> 5;
    int rt   = blockIdx.x;                          // row-tile (16 rows)
    int i0   = rt * 16;
    int n0   = wid * 64;                            // warp's 64 cols
    int ntb  = n0 >> 3;                             // first n-tile (of 8)

    const uint4* __restrict__ Ahi = g_ahi4;
    const uint4* __restrict__ Alo = g_alo4;
    const uint4* __restrict__ B4  = g_b4;

    // Preload ALL A fragments: 16 independent LDG.128 (one L2 trip, MLP=16)
    uint4 ah[8], al[8];
    #pragma unroll
    for (int kt = 0; kt < 8; kt++) {
        int base = (rt * 8 + kt) * 32 + lane;
        ah[kt] = __ldg(Ahi + base);
        al[kt] = __ldg(Alo + base);
    }

    float acc[8][4];
    #pragma unroll
    for (int nt = 0; nt < 8; nt++)
        #pragma unroll
        for (int c = 0; c < 4; c++) acc[nt][c] = 0.f;

    #pragma unroll
    for (int kt = 0; kt < 8; kt++) {
        #pragma unroll
        for (int nt = 0; nt < 8; nt++) {
            uint4 bv = __ldg(B4 + ((ntb + nt) * 8 + kt) * 32 + lane);
            MMA3(ah[kt].x, ah[kt].y, ah[kt].z, ah[kt].w, bv.x, bv.y, acc[nt]);
            MMA3(ah[kt].x, ah[kt].y, ah[kt].z, ah[kt].w, bv.z, bv.w, acc[nt]);
            MMA3(al[kt].x, al[kt].y, al[kt].z, al[kt].w, bv.x, bv.y, acc[nt]);
        }
    }

    // D layout: d0,d1 -> row r=lane/4, cols 2c,2c+1 (c=lane%4); d2,d3 -> row r+8
    int r = lane >> 2, c2 = 2 * (lane & 3);
    #pragma unroll
    for (int nt = 0; nt < 8; nt++) {
        int col = n0 + nt * 8 + c2;
        *(float2*)(out + (size_t)(i0 + r) * HD + col) =
            make_float2(acc[nt][0], acc[nt][1]);
        *(float2*)(out + (size_t)(i0 + r + 8) * HD + col) =
            make_float2(acc[nt][2], acc[nt][3]);
    }
}

extern "C" void kernel_launch(void* const* d_in, const int* in_sizes, int n_in,
                              void* d_out, int out_size) {
    const float* x  = (const float*)d_in[0];
    const void*  ei = d_in[1];
    const float* W  = (const float*)d_in[2];
    float*       out = (float*)d_out;

    k_scatter<<<(EE + 255) / 256, 256>>>(ei);
    k_post<<<PB_CLEAN + PB_SCALE + PB_WS, 256>>>(ei, x, W);
    k_aggregate<<<NN / 4, 256>>>();
    k_gemm_mma<<<NN / 16, 128>>>(out);
}

// round 15
// speedup vs baseline: 1.0703x; 1.0703x over previous
#include <cuda_runtime.h>
#include <cuda_bf16.h>
#include <cstdint>

#define NN 8192
#define EE 131072
#define ND 128
#define HD 256
#define NKP (ND / 2)                // 64 kpairs per row (u32 = 2 bf16)
#define ADJ_WORDS (NN * NN / 32)    // 8 MiB bitmap
#define MAXROW 64                   // distinct-degree cap (Poisson(16): P>=64 ~ 1e-20)

// Scratch (no allocations allowed — device globals per harness rules).
// INVARIANT across calls: g_adj all-zero and g_deg all-zero at entry.
// (bitmap re-zeroed inside k_gemm_mma; deg re-zeroed in k_aggregate.)
__device__ unsigned g_adj[ADJ_WORDS];
__device__ int      g_deg[NN];             // EXTRA distinct neighbors (true deg = +1)
__device__ int      g_nbr[NN * MAXROW];    // 2 MB compact adjacency
__device__ float    g_xs[NN * ND];
// Operands in VECTORIZED fragment-major layout: each lane's 4 m16n8k16 chunks
// are one contiguous uint4 -> single LDG.128 per fragment set.
//   A (hi/lo separate): g_a*4[(rt*8+kt)*32 + lane] = {a0,a1,a2,a3}
//   B (hi+lo packed):   g_b4 [(nt*8+kt)*32 + lane] = {bh0,bh1,bl0,bl1}
__device__ uint4 g_ahi4[NN * NKP / 4];
__device__ uint4 g_alo4[NN * NKP / 4];
__device__ uint4 g_b4[(HD / 8) * 8 * 32];
__device__ int   g_is64;

// ---------------------------------------------------------------------------
// Fragment addressing (u32-granular, for the writers).
// ---------------------------------------------------------------------------
__device__ __forceinline__ int a_u32(int i, int kp) {
    int rt = i >> 4, kt = kp >> 3;
    int r16 = i & 15, k8 = kp & 7;
    int chunk = ((k8 >> 2) << 1) | (r16 >> 3);
    int lane = (r16 & 7) * 4 + (k8 & 3);
    return (((rt * 8 + kt) * 32 + lane) << 2) + chunk;
}

// ---------------------------------------------------------------------------
// int64 vs int32 detection (values in [0,8192): int64 LE buffer has every odd
// 32-bit word == 0; int32 has random indices there).
// ---------------------------------------------------------------------------
__device__ __forceinline__ int detect_is64_block(const unsigned* ei, int* s_ok) {
    if (threadIdx.x == 0) *s_ok = 1;
    __syncthreads();
    if (threadIdx.x < 64 && ei[2 * threadIdx.x + 1] != 0u) *s_ok = 0;
    __syncthreads();
    return *s_ok;
}

__device__ __forceinline__ void decode_edge(const void* ei, int is64, int e,
                                            int& s, int& t) {
    if (is64) {
        const long long* p = (const long long*)ei;
        s = (int)p[e];
        t = (int)p[EE + e];
    } else {
        const int* p = (const int*)ei;
        s = p[e];
        t = p[EE + e];
    }
}

// split (vx, vy) into packed bf16x2 hi and lo
__device__ __forceinline__ void split2(float vx, float vy, uint32_t& hi, uint32_t& lo) {
    __nv_bfloat162 h2 = __floats2bfloat162_rn(vx, vy);
    float r0 = vx - __bfloat162float(__low2bfloat16(h2));
    float r1 = vy - __bfloat162float(__high2bfloat16(h2));
    __nv_bfloat162 l2 = __floats2bfloat162_rn(r0, r1);
    hi = *(uint32_t*)&h2;
    lo = *(uint32_t*)&l2;
}

__global__ void __launch_bounds__(256) k_scatter(const void* __restrict__ ei) {
    __shared__ int s_ok;
    int is64 = detect_is64_block((const unsigned*)ei, &s_ok);
    if (blockIdx.x == 0 && threadIdx.x == 0) g_is64 = is64;

    int e = blockIdx.x * blockDim.x + threadIdx.x;
    if (e >= EE) return;
    int s, t;
    decode_edge(ei, is64, e, s, t);
    unsigned idx  = (unsigned)s * NN + (unsigned)t;
    unsigned mask = 1u << (idx & 31u);
    unsigned old  = atomicOr(&g_adj[idx >> 5], mask);
    if (!(old & mask)) {
        int slot = atomicAdd(&g_deg[s], 1);
        if (slot < MAXROW) g_nbr[s * MAXROW + slot] = t;
    }
}

// Fused: xs = D^-1/2 x [0,512) + W split [512,576). (Bitmap cleanup moved
// into k_gemm_mma, where it hides in idle issue slots.)
#define PB_SCALE ((NN * ND / 8) / 256)         // 512
#define PB_WS    ((HD * NKP) / 256)            // 64
__global__ void __launch_bounds__(256) k_post(const float* __restrict__ x,
                                              const float* __restrict__ W) {
    if (blockIdx.x < PB_SCALE) {
        int gid = blockIdx.x * 256 + threadIdx.x;
        int q = 2 * gid;
        int i = q >> 5;
        float dinv = rsqrtf((float)(g_deg[i] + 1));
        float4 v0 = __ldg((const float4*)x + q);
        float4 v1 = __ldg((const float4*)x + q + 1);
        v0.x *= dinv; v0.y *= dinv; v0.z *= dinv; v0.w *= dinv;
        v1.x *= dinv; v1.y *= dinv; v1.z *= dinv; v1.w *= dinv;
        ((float4*)g_xs)[q]     = v0;
        ((float4*)g_xs)[q + 1] = v1;
    } else {
        int e = (blockIdx.x - PB_SCALE) * 256 + threadIdx.x;
        int h = e >> 6, p = e & 63;                           // col h, kpair p
        float2 v = *(const float2*)(W + (size_t)h * ND + 2 * p);
        uint32_t hi, lo; split2(v.x, v.y, hi, lo);
        int nt = h >> 3, kt = p >> 3;
        int n8 = h & 7, k8 = p & 7;
        int b = k8 >> 2;
        int lane = n8 * 4 + (k8 & 3);
        uint32_t* b4u = (uint32_t*)g_b4;
        int base = ((nt * 8 + kt) * 32 + lane) << 2;
        b4u[base + b]     = hi;
        b4u[base + 2 + b] = lo;
    }
}

// mid = A_hat @ x (two warps per row, half-split); epilogue writes the bf16
// hi/lo split of mid in vectorized fragment layout; resets g_deg (invariant).
__global__ void __launch_bounds__(256) k_aggregate() {
    __shared__ __align__(16) float4 part[4 * 32];
    int warp = threadIdx.x >> 5;
    int lane = threadIdx.x & 31;
    int r    = warp >> 1;
    int half = warp & 1;
    int i = blockIdx.x * 4 + r;

    int dext = g_deg[i];
    int n = min(dext, MAXROW);
    int k  = half ? (n >> 1) : 0;
    int k1 = half ? n        : (n >> 1);

    const float4* __restrict__ xs4 = (const float4*)g_xs;
    const int* __restrict__ lst = g_nbr + i * MAXROW;

    float4 acc = make_float4(0.f, 0.f, 0.f, 0.f);
    if (!half) acc = xs4[i * 32 + lane];

    for (; k + 7 < k1; k += 8) {
        int j0 = __ldg(lst + k + 0), j1 = __ldg(lst + k + 1);
        int j2 = __ldg(lst + k + 2), j3 = __ldg(lst + k + 3);
        int j4 = __ldg(lst + k + 4), j5 = __ldg(lst + k + 5);
        int j6 = __ldg(lst + k + 6), j7 = __ldg(lst + k + 7);
        float4 a0 = xs4[j0 * 32 + lane], a1 = xs4[j1 * 32 + lane];
        float4 a2 = xs4[j2 * 32 + lane], a3 = xs4[j3 * 32 + lane];
        float4 a4 = xs4[j4 * 32 + lane], a5 = xs4[j5 * 32 + lane];
        float4 a6 = xs4[j6 * 32 + lane], a7 = xs4[j7 * 32 + lane];
        acc.x += ((a0.x + a1.x) + (a2.x + a3.x)) + ((a4.x + a5.x) + (a6.x + a7.x));
        acc.y += ((a0.y + a1.y) + (a2.y + a3.y)) + ((a4.y + a5.y) + (a6.y + a7.y));
        acc.z += ((a0.z + a1.z) + (a2.z + a3.z)) + ((a4.z + a5.z) + (a6.z + a7.z));
        acc.w += ((a0.w + a1.w) + (a2.w + a3.w)) + ((a4.w + a5.w) + (a6.w + a7.w));
    }
    for (; k < k1; k++) {
        int j = __ldg(lst + k);
        float4 a = xs4[j * 32 + lane];
        acc.x += a.x; acc.y += a.y; acc.z += a.z; acc.w += a.w;
    }

    if (half) part[r * 32 + lane] = acc;
    __syncthreads();
    if (!half) {
        float4 p = part[r * 32 + lane];
        float dinv = rsqrtf((float)(dext + 1));
        acc.x = (acc.x + p.x) * dinv;
        acc.y = (acc.y + p.y) * dinv;
        acc.z = (acc.z + p.z) * dinv;
        acc.w = (acc.w + p.w) * dinv;
        uint32_t h0, l0, h1, l1;
        split2(acc.x, acc.y, h0, l0);              // kpair 2*lane
        split2(acc.z, acc.w, h1, l1);              // kpair 2*lane+1
        uint32_t* ahi = (uint32_t*)g_ahi4;
        uint32_t* alo = (uint32_t*)g_alo4;
        int a0 = a_u32(i, 2 * lane);
        int a1 = a_u32(i, 2 * lane + 1);
        ahi[a0] = h0; ahi[a1] = h1;
        alo[a0] = l0; alo[a1] = l1;
        if (lane == 0) g_deg[i] = 0;
    }
}

// ===========================================================================
// HMMA GEMM — EXACT R12 structure (measured best: 12.0us). CTA = 32 rows x
// 256 cols, 4 warps; warp = 32 rows (2 m16 tiles) x 64 cols (8 n8 tiles).
// Vectorized fragment loads (uint4 = 4 chunks). 3-pass bf16 split, fp32 acc.
// PLUS: bitmap cleanup folded in (4 edges/thread) — hides in the idle issue
// slots (R12-R14 all showed issue 5-7%: latency/rate-bound, slack to spare).
// ===========================================================================
#define MMA3(A0,A1,A2,A3, B0,B1, C)                                          \
    asm volatile("mma.sync.aligned.m16n8k16.row.col.f32.bf16.bf16.f32 "      \
        "{%0,%1,%2,%3},{%4,%5,%6,%7},{%8,%9},{%0,%1,%2,%3};"                 \
        : "+f"(C[0]), "+f"(C[1]), "+f"(C[2]), "+f"(C[3])                     \
        : "r"(A0), "r"(A1), "r"(A2), "r"(A3), "r"(B0), "r"(B1))

__global__ void __launch_bounds__(128) k_gemm_mma(const void* __restrict__ ei,
                                                  float* __restrict__ out) {
    // ---- folded bitmap cleanup: 32768 threads x 4 edges = 131072 ----
    {
        int g = blockIdx.x * 128 + threadIdx.x;
        int is64 = g_is64;
        #pragma unroll
        for (int q = 0; q < 4; q++) {
            int e = g + q * 32768;
            int s, t;
            decode_edge(ei, is64, e, s, t);
            g_adj[((unsigned)s * NN + (unsigned)t) >> 5] = 0u;  // races benign
        }
    }

    int lane = threadIdx.x & 31;
    int wid  = threadIdx.x >> 5;
    int i0 = blockIdx.x * 32;                       // CTA's 32 rows
    int n0 = wid * 64;                              // warp's 64 cols
    int rt0 = i0 >> 4;                              // first row-tile (of 2)
    int ntb = n0 >> 3;                              // first n-tile (of 8)

    float acc[2][8][4];
    #pragma unroll
    for (int rr = 0; rr < 2; rr++)
        #pragma unroll
        for (int nt = 0; nt < 8; nt++)
            #pragma unroll
            for (int c = 0; c < 4; c++) acc[rr][nt][c] = 0.f;

    const uint4* __restrict__ Ahi = g_ahi4;
    const uint4* __restrict__ Alo = g_alo4;
    const uint4* __restrict__ B4  = g_b4;

    #pragma unroll 1
    for (int kt = 0; kt < 8; kt++) {
        uint4 ah[2], al[2];
        #pragma unroll
        for (int rr = 0; rr < 2; rr++) {
            int base = ((rt0 + rr) * 8 + kt) * 32 + lane;
            ah[rr] = __ldg(Ahi + base);
            al[rr] = __ldg(Alo + base);
        }
        #pragma unroll
        for (int nt = 0; nt < 8; nt++) {
            uint4 bv = __ldg(B4 + ((ntb + nt) * 8 + kt) * 32 + lane);
            #pragma unroll
            for (int rr = 0; rr < 2; rr++) {
                MMA3(ah[rr].x, ah[rr].y, ah[rr].z, ah[rr].w, bv.x, bv.y, acc[rr][nt]);
                MMA3(ah[rr].x, ah[rr].y, ah[rr].z, ah[rr].w, bv.z, bv.w, acc[rr][nt]);
                MMA3(al[rr].x, al[rr].y, al[rr].z, al[rr].w, bv.x, bv.y, acc[rr][nt]);
            }
        }
    }

    // D layout: d0,d1 -> row r=lane/4, cols 2c,2c+1 (c=lane%4); d2,d3 -> row r+8
    int r = lane >> 2, c2 = 2 * (lane & 3);
    #pragma unroll
    for (int rr = 0; rr < 2; rr++)
        #pragma unroll
        for (int nt = 0; nt < 8; nt++) {
            int col = n0 + nt * 8 + c2;
            int row = i0 + rr * 16 + r;
            *(float2*)(out + (size_t)row * HD + col) =
                make_float2(acc[rr][nt][0], acc[rr][nt][1]);
            *(float2*)(out + (size_t)(row + 8) * HD + col) =
                make_float2(acc[rr][nt][2], acc[rr][nt][3]);
        }
}

extern "C" void kernel_launch(void* const* d_in, const int* in_sizes, int n_in,
                              void* d_out, int out_size) {
    const float* x  = (const float*)d_in[0];
    const void*  ei = d_in[1];
    const float* W  = (const float*)d_in[2];
    float*       out = (float*)d_out;

    k_scatter<<<(EE + 255) / 256, 256>>>(ei);
    k_post<<<PB_SCALE + PB_WS, 256>>>(x, W);
    k_aggregate<<<NN / 4, 256>>>();
    k_gemm_mma<<<NN / 32, 128>>>(ei, out);
}